// round 6
// baseline (speedup 1.0000x reference)
#include <cuda_runtime.h>
#include <math.h>

#define N_ATOMS 16384
#define N_EDGES 262144
#define HID 128
#define NG 50
#define NINTER 6

// ---------------- scratch (static device globals; no allocation) ----------------
__device__ float g_ea[N_EDGES * NG];     // 52.4 MB  gaussian smearing, iteration-invariant
__device__ float g_C[N_EDGES];           // cosine cutoff
__device__ float g_h[N_ATOMS * HID];     // node features
__device__ float g_x[N_ATOMS * HID];     // lin1 output
__device__ float g_agg[N_ATOMS * HID];   // scatter-sum target
__device__ float g_bsum[128];            // readout partials

// ---------------- helpers ----------------
__device__ __forceinline__ unsigned long long pack2(float lo, float hi) {
    unsigned long long r;
    asm("mov.b64 %0, {%1, %2};" : "=l"(r) : "f"(lo), "f"(hi));
    return r;
}
__device__ __forceinline__ void fma2(unsigned long long& d, unsigned long long a, unsigned long long b) {
    asm("fma.rn.f32x2 %0, %1, %2, %0;" : "+l"(d) : "l"(a), "l"(b));
}
__device__ __forceinline__ float2 unpack2(unsigned long long v) {
    float2 f;
    asm("mov.b64 {%0, %1}, %2;" : "=f"(f.x), "=f"(f.y) : "l"(v));
    return f;
}
__device__ __forceinline__ float sspf(float x) {
    // shifted softplus: log(1+e^x) - log(2), numerically stable
    return fmaxf(x, 0.0f) + log1pf(__expf(-fabsf(x))) - 0.6931471805599453f;
}

// ---------------- K0: per-edge geometry (once per launch) ----------------
__global__ __launch_bounds__(256) void geom_kernel(const int* __restrict__ ei,
                                                   const float* __restrict__ pos) {
    int idx = blockIdx.x * 256 + threadIdx.x;          // E*NG threads
    int e = idx / NG;
    int g = idx - e * NG;
    int s = ei[e];
    int d = ei[N_EDGES + e];
    float dx = pos[s * 3 + 0] - pos[d * 3 + 0];
    float dy = pos[s * 3 + 1] - pos[d * 3 + 1];
    float dz = pos[s * 3 + 2] - pos[d * 3 + 2];
    float dist = sqrtf(dx * dx + dy * dy + dz * dz);
    const float delta = 10.0f / 49.0f;
    const float coeff = -0.5f / (delta * delta);
    float t = dist - (float)g * delta;
    g_ea[idx] = __expf(coeff * t * t);
    if (g == 0) g_C[e] = 0.5f * (__cosf(dist * 0.31415926535897931f) + 1.0f);
}

// ---------------- K0b: h = emb[z] ----------------
__global__ __launch_bounds__(256) void init_h_kernel(const int* __restrict__ z,
                                                     const float* __restrict__ emb) {
    int idx = blockIdx.x * 256 + threadIdx.x;          // N*HID threads
    int n = idx >> 7;
    int c = idx & 127;
    g_h[idx] = emb[z[n] * HID + c];
}

// ---------------- K1: x = h @ Wl1[i]  (no bias); also zeroes g_agg rows ----------------
// 64 rows/block, 256 threads: thread = 2 rows x 16 cols, f32x2 FMA
#define SMEM_LIN1 ((16384 + 64 * 132) * 4)
__global__ __launch_bounds__(256) void lin1_kernel(const float* __restrict__ W) {
    extern __shared__ float sm[];
    float* sW = sm;                 // 128x128
    float* sH = sW + 16384;         // 64x132 (padded)
    int tid = threadIdx.x;
    int r0b = blockIdx.x * 64;

    // zero the agg rows this block owns (replaces cudaMemsetAsync; edge kernel
    // runs strictly after this kernel on the same stream)
    {
        float4 z4 = make_float4(0.f, 0.f, 0.f, 0.f);
        float4* ap = (float4*)(g_agg + (size_t)r0b * HID);
        for (int idx = tid; idx < 2048; idx += 256) ap[idx] = z4;
    }

    for (int idx = tid; idx < 4096; idx += 256)
        ((float4*)sW)[idx] = ((const float4*)W)[idx];
    {
        const float4* hsrc = (const float4*)(g_h + (size_t)r0b * HID);
        for (int idx = tid; idx < 2048; idx += 256) {
            int r = idx >> 5, q = idx & 31;
            ((float4*)(sH + r * 132))[q] = hsrc[idx];
        }
    }
    __syncthreads();

    int cg = tid & 7, rg = tid >> 3;
    int c0 = cg * 16, r0 = rg * 2;

    unsigned long long acc[2][8];
#pragma unroll
    for (int r = 0; r < 2; r++)
#pragma unroll
        for (int j = 0; j < 8; j++) acc[r][j] = 0ull;

#pragma unroll 4
    for (int k = 0; k < HID; k++) {
        unsigned long long a2[2];
#pragma unroll
        for (int r = 0; r < 2; r++) {
            float a = sH[(r0 + r) * 132 + k];
            a2[r] = pack2(a, a);
        }
        const ulonglong2* wp = (const ulonglong2*)(sW + k * HID + c0);
        ulonglong2 w01 = wp[0], w23 = wp[1], w45 = wp[2], w67 = wp[3];
#pragma unroll
        for (int r = 0; r < 2; r++) {
            fma2(acc[r][0], a2[r], w01.x); fma2(acc[r][1], a2[r], w01.y);
            fma2(acc[r][2], a2[r], w23.x); fma2(acc[r][3], a2[r], w23.y);
            fma2(acc[r][4], a2[r], w45.x); fma2(acc[r][5], a2[r], w45.y);
            fma2(acc[r][6], a2[r], w67.x); fma2(acc[r][7], a2[r], w67.y);
        }
    }
#pragma unroll
    for (int r = 0; r < 2; r++) {
        float4* op = (float4*)(g_x + (size_t)(r0b + r0 + r) * HID + c0);
#pragma unroll
        for (int q = 0; q < 4; q++) {
            float2 p0 = unpack2(acc[r][2 * q]);
            float2 p1 = unpack2(acc[r][2 * q + 1]);
            float4 v; v.x = p0.x; v.y = p0.y; v.z = p1.x; v.w = p1.y;
            op[q] = v;
        }
    }
}

// ---------------- K2: fused edge kernel ----------------
// per block: 128 edges, 512 threads. Wfilt = (ssp(ea@Wf1+b1)@Wf2+b2)*C,
// msg = x[src]*Wfilt, atomicAdd into agg[dst].
#define SMEM_EDGE ((6400 + 16384 + 128 * 52 + 128 * 132 + 3 * 128) * 4 + 256 * 4)
__global__ __launch_bounds__(512) void edge_kernel(const float* __restrict__ Wf1,
                                                   const float* __restrict__ bf1,
                                                   const float* __restrict__ Wf2,
                                                   const float* __restrict__ bf2,
                                                   const int* __restrict__ ei) {
    extern __shared__ float sm[];
    float* sW1 = sm;                       // 50x128
    float* sW2 = sW1 + 6400;               // 128x128
    float* sEA = sW2 + 16384;              // 128x52 (padded)
    float* sT  = sEA + 128 * 52;           // 128x132 (padded)
    float* sC  = sT + 128 * 132;
    float* sB1 = sC + 128;
    float* sB2 = sB1 + 128;
    int* sSrc  = (int*)(sB2 + 128);
    int* sDst  = sSrc + 128;

    int tid = threadIdx.x;
    int e0b = blockIdx.x * 128;

    for (int idx = tid; idx < 1600; idx += 512)
        ((float4*)sW1)[idx] = ((const float4*)Wf1)[idx];
    for (int idx = tid; idx < 4096; idx += 512)
        ((float4*)sW2)[idx] = ((const float4*)Wf2)[idx];
    for (int idx = tid; idx < 128 * NG; idx += 512) {
        int e = idx / NG, k = idx - e * NG;
        sEA[e * 52 + k] = g_ea[(size_t)e0b * NG + idx];
    }
    if (tid < 128) {
        sC[tid]  = g_C[e0b + tid];
        sB1[tid] = bf1[tid];
        sB2[tid] = bf2[tid];
        sSrc[tid] = ei[e0b + tid];
        sDst[tid] = ei[N_EDGES + e0b + tid];
    }
    __syncthreads();

    int cg = tid & 7, eg = tid >> 3;   // 8 col-groups x 64 edge-groups
    int c0 = cg * 16, e0 = eg * 2;

    unsigned long long acc[2][8];
#pragma unroll
    for (int e = 0; e < 2; e++)
#pragma unroll
        for (int j = 0; j < 8; j++) acc[e][j] = 0ull;

    // ---- phase 1: T = ssp(EA @ W1 + b1) ----
#pragma unroll 5
    for (int k = 0; k < NG; k++) {
        unsigned long long a2[2];
#pragma unroll
        for (int e = 0; e < 2; e++) {
            float a = sEA[(e0 + e) * 52 + k];
            a2[e] = pack2(a, a);
        }
        const ulonglong2* wp = (const ulonglong2*)(sW1 + k * 128 + c0);
        ulonglong2 w01 = wp[0], w23 = wp[1], w45 = wp[2], w67 = wp[3];
#pragma unroll
        for (int e = 0; e < 2; e++) {
            fma2(acc[e][0], a2[e], w01.x); fma2(acc[e][1], a2[e], w01.y);
            fma2(acc[e][2], a2[e], w23.x); fma2(acc[e][3], a2[e], w23.y);
            fma2(acc[e][4], a2[e], w45.x); fma2(acc[e][5], a2[e], w45.y);
            fma2(acc[e][6], a2[e], w67.x); fma2(acc[e][7], a2[e], w67.y);
        }
    }
#pragma unroll
    for (int e = 0; e < 2; e++) {
        float* trow = sT + (e0 + e) * 132 + c0;
#pragma unroll
        for (int q = 0; q < 4; q++) {
            float2 p0 = unpack2(acc[e][2 * q]);
            float2 p1 = unpack2(acc[e][2 * q + 1]);
            float4 v;
            v.x = sspf(p0.x + sB1[c0 + 4 * q + 0]);
            v.y = sspf(p0.y + sB1[c0 + 4 * q + 1]);
            v.z = sspf(p1.x + sB1[c0 + 4 * q + 2]);
            v.w = sspf(p1.y + sB1[c0 + 4 * q + 3]);
            ((float4*)trow)[q] = v;
        }
    }
    __syncthreads();

    // ---- phase 2: Wf = (T @ W2 + b2)*C; msg = x[src]*Wf; atomicAdd into agg[dst] ----
#pragma unroll
    for (int e = 0; e < 2; e++)
#pragma unroll
        for (int j = 0; j < 8; j++) acc[e][j] = 0ull;

#pragma unroll 4
    for (int k = 0; k < HID; k++) {
        unsigned long long a2[2];
#pragma unroll
        for (int e = 0; e < 2; e++) {
            float a = sT[(e0 + e) * 132 + k];
            a2[e] = pack2(a, a);
        }
        const ulonglong2* wp = (const ulonglong2*)(sW2 + k * 128 + c0);
        ulonglong2 w01 = wp[0], w23 = wp[1], w45 = wp[2], w67 = wp[3];
#pragma unroll
        for (int e = 0; e < 2; e++) {
            fma2(acc[e][0], a2[e], w01.x); fma2(acc[e][1], a2[e], w01.y);
            fma2(acc[e][2], a2[e], w23.x); fma2(acc[e][3], a2[e], w23.y);
            fma2(acc[e][4], a2[e], w45.x); fma2(acc[e][5], a2[e], w45.y);
            fma2(acc[e][6], a2[e], w67.x); fma2(acc[e][7], a2[e], w67.y);
        }
    }
#pragma unroll
    for (int e = 0; e < 2; e++) {
        int le = e0 + e;
        float Cv = sC[le];
        int s = sSrc[le];
        int d = sDst[le];
        const float4* xp = (const float4*)(g_x + (size_t)s * HID + c0);
        float* ap = g_agg + (size_t)d * HID + c0;
#pragma unroll
        for (int q = 0; q < 4; q++) {
            float2 p0 = unpack2(acc[e][2 * q]);
            float2 p1 = unpack2(acc[e][2 * q + 1]);
            float4 xv = xp[q];
            atomicAdd(ap + 4 * q + 0, (p0.x + sB2[c0 + 4 * q + 0]) * Cv * xv.x);
            atomicAdd(ap + 4 * q + 1, (p0.y + sB2[c0 + 4 * q + 1]) * Cv * xv.y);
            atomicAdd(ap + 4 * q + 2, (p1.x + sB2[c0 + 4 * q + 2]) * Cv * xv.z);
            atomicAdd(ap + 4 * q + 3, (p1.y + sB2[c0 + 4 * q + 3]) * Cv * xv.w);
        }
    }
}

// ---------------- K3: h = h + ssp(agg @ Wl2 + bl2) @ Wl + bl ----------------
#define SMEM_NODE ((2 * 16384 + 2 * 64 * 132 + 256) * 4)
__global__ __launch_bounds__(256) void node_kernel(const float* __restrict__ Wl2,
                                                   const float* __restrict__ bl2,
                                                   const float* __restrict__ Wl,
                                                   const float* __restrict__ bl) {
    extern __shared__ float sm[];
    float* sWa = sm;                   // Wl2 128x128
    float* sWb = sWa + 16384;          // Wl  128x128
    float* sA  = sWb + 16384;          // 64x132
    float* sM  = sA + 64 * 132;        // 64x132
    float* sB2 = sM + 64 * 132;
    float* sB  = sB2 + 128;

    int tid = threadIdx.x;
    int r0b = blockIdx.x * 64;

    for (int idx = tid; idx < 4096; idx += 256)
        ((float4*)sWa)[idx] = ((const float4*)Wl2)[idx];
    for (int idx = tid; idx < 4096; idx += 256)
        ((float4*)sWb)[idx] = ((const float4*)Wl)[idx];
    {
        const float4* asrc = (const float4*)(g_agg + (size_t)r0b * HID);
        for (int idx = tid; idx < 2048; idx += 256) {
            int r = idx >> 5, q = idx & 31;
            ((float4*)(sA + r * 132))[q] = asrc[idx];
        }
    }
    if (tid < 128) { sB2[tid] = bl2[tid]; sB[tid] = bl[tid]; }
    __syncthreads();

    int cg = tid & 7, rg = tid >> 3;
    int c0 = cg * 16, r0 = rg * 2;

    unsigned long long acc[2][8];
#pragma unroll
    for (int r = 0; r < 2; r++)
#pragma unroll
        for (int j = 0; j < 8; j++) acc[r][j] = 0ull;

#pragma unroll 4
    for (int k = 0; k < HID; k++) {
        unsigned long long a2[2];
#pragma unroll
        for (int r = 0; r < 2; r++) {
            float a = sA[(r0 + r) * 132 + k];
            a2[r] = pack2(a, a);
        }
        const ulonglong2* wp = (const ulonglong2*)(sWa + k * HID + c0);
        ulonglong2 w01 = wp[0], w23 = wp[1], w45 = wp[2], w67 = wp[3];
#pragma unroll
        for (int r = 0; r < 2; r++) {
            fma2(acc[r][0], a2[r], w01.x); fma2(acc[r][1], a2[r], w01.y);
            fma2(acc[r][2], a2[r], w23.x); fma2(acc[r][3], a2[r], w23.y);
            fma2(acc[r][4], a2[r], w45.x); fma2(acc[r][5], a2[r], w45.y);
            fma2(acc[r][6], a2[r], w67.x); fma2(acc[r][7], a2[r], w67.y);
        }
    }
#pragma unroll
    for (int r = 0; r < 2; r++) {
        float* mrow = sM + (r0 + r) * 132 + c0;
#pragma unroll
        for (int q = 0; q < 4; q++) {
            float2 p0 = unpack2(acc[r][2 * q]);
            float2 p1 = unpack2(acc[r][2 * q + 1]);
            float4 v;
            v.x = sspf(p0.x + sB2[c0 + 4 * q + 0]);
            v.y = sspf(p0.y + sB2[c0 + 4 * q + 1]);
            v.z = sspf(p1.x + sB2[c0 + 4 * q + 2]);
            v.w = sspf(p1.y + sB2[c0 + 4 * q + 3]);
            ((float4*)mrow)[q] = v;
        }
    }
    __syncthreads();

#pragma unroll
    for (int r = 0; r < 2; r++)
#pragma unroll
        for (int j = 0; j < 8; j++) acc[r][j] = 0ull;

#pragma unroll 4
    for (int k = 0; k < HID; k++) {
        unsigned long long a2[2];
#pragma unroll
        for (int r = 0; r < 2; r++) {
            float a = sM[(r0 + r) * 132 + k];
            a2[r] = pack2(a, a);
        }
        const ulonglong2* wp = (const ulonglong2*)(sWb + k * HID + c0);
        ulonglong2 w01 = wp[0], w23 = wp[1], w45 = wp[2], w67 = wp[3];
#pragma unroll
        for (int r = 0; r < 2; r++) {
            fma2(acc[r][0], a2[r], w01.x); fma2(acc[r][1], a2[r], w01.y);
            fma2(acc[r][2], a2[r], w23.x); fma2(acc[r][3], a2[r], w23.y);
            fma2(acc[r][4], a2[r], w45.x); fma2(acc[r][5], a2[r], w45.y);
            fma2(acc[r][6], a2[r], w67.x); fma2(acc[r][7], a2[r], w67.y);
        }
    }
#pragma unroll
    for (int r = 0; r < 2; r++) {
        float4* hp = (float4*)(g_h + (size_t)(r0b + r0 + r) * HID + c0);
#pragma unroll
        for (int q = 0; q < 4; q++) {
            float2 p0 = unpack2(acc[r][2 * q]);
            float2 p1 = unpack2(acc[r][2 * q + 1]);
            float4 h = hp[q];
            h.x += p0.x + sB[c0 + 4 * q + 0];
            h.y += p0.y + sB[c0 + 4 * q + 1];
            h.z += p1.x + sB[c0 + 4 * q + 2];
            h.w += p1.y + sB[c0 + 4 * q + 3];
            hp[q] = h;
        }
    }
}

// ---------------- K4: per-atom readout, per-block partial sums ----------------
__global__ __launch_bounds__(128) void readout_kernel(const float* __restrict__ Wo1,
                                                      const float* __restrict__ bo1,
                                                      const float* __restrict__ Wo2) {
    __shared__ float sW[128 * 64];
    __shared__ float sw2[64];
    __shared__ float sb1[64];
    __shared__ float wsum[4];
    int tid = threadIdx.x;
    for (int idx = tid; idx < 2048; idx += 128)
        ((float4*)sW)[idx] = ((const float4*)Wo1)[idx];
    if (tid < 64) { sw2[tid] = Wo2[tid]; sb1[tid] = bo1[tid]; }
    __syncthreads();

    int atom = blockIdx.x * 128 + tid;
    float acc[64];
#pragma unroll
    for (int j = 0; j < 64; j++) acc[j] = 0.0f;
    const float4* hp = (const float4*)(g_h + (size_t)atom * HID);
#pragma unroll 2
    for (int k4 = 0; k4 < 32; k4++) {
        float4 hv = hp[k4];
        const float* w0 = sW + (k4 * 4) * 64;
#pragma unroll
        for (int j = 0; j < 64; j++)
            acc[j] += hv.x * w0[j] + hv.y * w0[64 + j] + hv.z * w0[128 + j] + hv.w * w0[192 + j];
    }
    float s = 0.0f;
#pragma unroll
    for (int j = 0; j < 64; j++) s += sspf(acc[j] + sb1[j]) * sw2[j];

    for (int o = 16; o > 0; o >>= 1) s += __shfl_down_sync(0xffffffffu, s, o);
    if ((tid & 31) == 0) wsum[tid >> 5] = s;
    __syncthreads();
    if (tid == 0) g_bsum[blockIdx.x] = wsum[0] + wsum[1] + wsum[2] + wsum[3];
}

__global__ void finalize_kernel(const float* __restrict__ bo2, float* __restrict__ out) {
    __shared__ float ws[4];
    int tid = threadIdx.x;  // 128
    float v = g_bsum[tid];
    for (int o = 16; o > 0; o >>= 1) v += __shfl_down_sync(0xffffffffu, v, o);
    if ((tid & 31) == 0) ws[tid >> 5] = v;
    __syncthreads();
    if (tid == 0) {
        float t = ws[0] + ws[1] + ws[2] + ws[3] + (float)N_ATOMS * bo2[0];
        out[0] = fmaxf(t, 0.0f);
    }
}

// ---------------- launch ----------------
extern "C" void kernel_launch(void* const* d_in, const int* in_sizes, int n_in,
                              void* d_out, int out_size) {
    const int*   z    = (const int*)d_in[0];
    const float* pos  = (const float*)d_in[1];
    const int*   ei   = (const int*)d_in[2];
    const float* emb  = (const float*)d_in[3];
    const float* Wf1  = (const float*)d_in[4];
    const float* bf1  = (const float*)d_in[5];
    const float* Wf2  = (const float*)d_in[6];
    const float* bf2  = (const float*)d_in[7];
    const float* Wl1  = (const float*)d_in[8];
    const float* Wl2  = (const float*)d_in[9];
    const float* bl2  = (const float*)d_in[10];
    const float* Wl   = (const float*)d_in[11];
    const float* bl   = (const float*)d_in[12];
    const float* Wo1  = (const float*)d_in[13];
    const float* bo1  = (const float*)d_in[14];
    const float* Wo2  = (const float*)d_in[15];
    const float* bo2  = (const float*)d_in[16];
    float* out = (float*)d_out;

    cudaFuncSetAttribute(lin1_kernel, cudaFuncAttributeMaxDynamicSharedMemorySize, SMEM_LIN1);
    cudaFuncSetAttribute(edge_kernel, cudaFuncAttributeMaxDynamicSharedMemorySize, SMEM_EDGE);
    cudaFuncSetAttribute(node_kernel, cudaFuncAttributeMaxDynamicSharedMemorySize, SMEM_NODE);

    geom_kernel<<<(N_EDGES * NG) / 256, 256>>>(ei, pos);
    init_h_kernel<<<(N_ATOMS * HID) / 256, 256>>>(z, emb);

    for (int i = 0; i < NINTER; i++) {
        lin1_kernel<<<N_ATOMS / 64, 256, SMEM_LIN1>>>(Wl1 + i * 16384);
        edge_kernel<<<N_EDGES / 128, 512, SMEM_EDGE>>>(Wf1 + i * 6400, bf1 + i * 128,
                                                       Wf2 + i * 16384, bf2 + i * 128, ei);
        node_kernel<<<N_ATOMS / 64, 256, SMEM_NODE>>>(Wl2 + i * 16384, bl2 + i * 128,
                                                      Wl + i * 16384, bl + i * 128);
    }
    readout_kernel<<<N_ATOMS / 128, 128>>>(Wo1, bo1, Wo2);
    finalize_kernel<<<1, 128>>>(bo2, out);
}

// round 7
// speedup vs baseline: 2.4632x; 2.4632x over previous
#include <cuda_runtime.h>
#include <math.h>

#define N_ATOMS 16384
#define N_EDGES 262144
#define HID 128
#define NG 50
#define NINTER 6

// padded strides (in floats) for conflict-free smem access
#define W_S  160   // weight row stride: 8 groups of 16 floats, each group padded to 20
#define EA_S 53    // ea tile row stride (odd -> distinct banks across row-groups)
#define T_S  133   // intermediate tile row stride (odd)
#define H_S  132   // node-side activation stride (multiple of 4 for float4 stores)

// ---------------- scratch (static device globals; no allocation) ----------------
__device__ float g_ea[N_EDGES * NG];     // 52.4 MB  gaussian smearing, iteration-invariant
__device__ float g_C[N_EDGES];           // cosine cutoff
__device__ float g_h[N_ATOMS * HID];     // node features
__device__ float g_x[N_ATOMS * HID];     // lin1 output
__device__ float g_agg[N_ATOMS * HID];   // scatter-sum target
__device__ float g_bsum[128];            // readout partials

// ---------------- helpers ----------------
__device__ __forceinline__ unsigned long long pack2(float lo, float hi) {
    unsigned long long r;
    asm("mov.b64 %0, {%1, %2};" : "=l"(r) : "f"(lo), "f"(hi));
    return r;
}
__device__ __forceinline__ void fma2(unsigned long long& d, unsigned long long a, unsigned long long b) {
    asm("fma.rn.f32x2 %0, %1, %2, %0;" : "+l"(d) : "l"(a), "l"(b));
}
__device__ __forceinline__ float2 unpack2(unsigned long long v) {
    float2 f;
    asm("mov.b64 {%0, %1}, %2;" : "=f"(f.x), "=f"(f.y) : "l"(v));
    return f;
}
__device__ __forceinline__ float sspf(float x) {
    return fmaxf(x, 0.0f) + log1pf(__expf(-fabsf(x))) - 0.6931471805599453f;
}

// copy an n x 128 row-major weight matrix into padded layout (row stride W_S,
// group g at offset g*20). nThreads = blockDim.x. n4 = n*32 float4 elements.
__device__ __forceinline__ void load_w_padded(float* dst, const float* src, int n4, int tid, int nthr) {
    const float4* s4 = (const float4*)src;
    for (int idx = tid; idx < n4; idx += nthr) {
        int row = idx >> 5, q = idx & 31;
        int g = q >> 2, o = q & 3;
        ((float4*)(dst + row * W_S + g * 20))[o] = s4[idx];
    }
}

// ---------------- K0: per-edge geometry (once per launch) ----------------
__global__ __launch_bounds__(256) void geom_kernel(const int* __restrict__ ei,
                                                   const float* __restrict__ pos) {
    int idx = blockIdx.x * 256 + threadIdx.x;          // E*NG threads
    int e = idx / NG;
    int g = idx - e * NG;
    int s = ei[e];
    int d = ei[N_EDGES + e];
    float dx = pos[s * 3 + 0] - pos[d * 3 + 0];
    float dy = pos[s * 3 + 1] - pos[d * 3 + 1];
    float dz = pos[s * 3 + 2] - pos[d * 3 + 2];
    float dist = sqrtf(dx * dx + dy * dy + dz * dz);
    const float delta = 10.0f / 49.0f;
    const float coeff = -0.5f / (delta * delta);
    float t = dist - (float)g * delta;
    g_ea[idx] = __expf(coeff * t * t);
    if (g == 0) g_C[e] = 0.5f * (__cosf(dist * 0.31415926535897931f) + 1.0f);
}

// ---------------- K0b: h = emb[z] ----------------
__global__ __launch_bounds__(256) void init_h_kernel(const int* __restrict__ z,
                                                     const float* __restrict__ emb) {
    int idx = blockIdx.x * 256 + threadIdx.x;          // N*HID threads
    int n = idx >> 7;
    int c = idx & 127;
    g_h[idx] = emb[z[n] * HID + c];
}

// ---------------- K1: x = h @ Wl1[i]; also zeroes g_agg rows ----------------
// 64 rows/block, 256 threads: thread = 2 rows x 16 cols, f32x2 FMA
#define SMEM_LIN1 ((128 * W_S + 64 * H_S) * 4)
__global__ __launch_bounds__(256) void lin1_kernel(const float* __restrict__ W) {
    extern __shared__ float sm[];
    float* sW = sm;                 // 128 x W_S (padded groups)
    float* sH = sW + 128 * W_S;     // 64 x H_S
    int tid = threadIdx.x;
    int r0b = blockIdx.x * 64;

    // zero agg rows this block owns (edge kernel runs strictly after on same stream)
    {
        float4 z4 = make_float4(0.f, 0.f, 0.f, 0.f);
        float4* ap = (float4*)(g_agg + (size_t)r0b * HID);
        for (int idx = tid; idx < 2048; idx += 256) ap[idx] = z4;
    }

    load_w_padded(sW, W, 4096, tid, 256);
    {
        const float4* hsrc = (const float4*)(g_h + (size_t)r0b * HID);
        for (int idx = tid; idx < 2048; idx += 256) {
            int r = idx >> 5, q = idx & 31;
            ((float4*)(sH + r * H_S))[q] = hsrc[idx];
        }
    }
    __syncthreads();

    int cg = tid & 7, rg = tid >> 3;
    int c0 = cg * 16, r0 = rg * 2;
    int wg = cg * 20;

    unsigned long long acc[2][8];
#pragma unroll
    for (int r = 0; r < 2; r++)
#pragma unroll
        for (int j = 0; j < 8; j++) acc[r][j] = 0ull;

#pragma unroll 4
    for (int k = 0; k < HID; k++) {
        unsigned long long a2[2];
#pragma unroll
        for (int r = 0; r < 2; r++) {
            float a = sH[(r0 + r) * H_S + k];
            a2[r] = pack2(a, a);
        }
        const ulonglong2* wp = (const ulonglong2*)(sW + k * W_S + wg);
        ulonglong2 w01 = wp[0], w23 = wp[1], w45 = wp[2], w67 = wp[3];
#pragma unroll
        for (int r = 0; r < 2; r++) {
            fma2(acc[r][0], a2[r], w01.x); fma2(acc[r][1], a2[r], w01.y);
            fma2(acc[r][2], a2[r], w23.x); fma2(acc[r][3], a2[r], w23.y);
            fma2(acc[r][4], a2[r], w45.x); fma2(acc[r][5], a2[r], w45.y);
            fma2(acc[r][6], a2[r], w67.x); fma2(acc[r][7], a2[r], w67.y);
        }
    }
#pragma unroll
    for (int r = 0; r < 2; r++) {
        float4* op = (float4*)(g_x + (size_t)(r0b + r0 + r) * HID + c0);
#pragma unroll
        for (int q = 0; q < 4; q++) {
            float2 p0 = unpack2(acc[r][2 * q]);
            float2 p1 = unpack2(acc[r][2 * q + 1]);
            float4 v; v.x = p0.x; v.y = p0.y; v.z = p1.x; v.w = p1.y;
            op[q] = v;
        }
    }
}

// ---------------- K2: fused edge kernel ----------------
// per block: 128 edges, 512 threads. Wfilt = (ssp(ea@Wf1+b1)@Wf2+b2)*C,
// msg = x[src]*Wfilt, atomicAdd into agg[dst].
#define SMEM_EDGE ((50 * W_S + 128 * W_S + 128 * EA_S + 128 * T_S + 3 * 128 + 256) * 4)
__global__ __launch_bounds__(512) void edge_kernel(const float* __restrict__ Wf1,
                                                   const float* __restrict__ bf1,
                                                   const float* __restrict__ Wf2,
                                                   const float* __restrict__ bf2,
                                                   const int* __restrict__ ei) {
    extern __shared__ float sm[];
    float* sW1 = sm;                        // 50 x W_S
    float* sW2 = sW1 + 50 * W_S;            // 128 x W_S
    float* sEA = sW2 + 128 * W_S;           // 128 x EA_S
    float* sT  = sEA + 128 * EA_S;          // 128 x T_S
    float* sC  = sT + 128 * T_S;
    float* sB1 = sC + 128;
    float* sB2 = sB1 + 128;
    int* sSrc  = (int*)(sB2 + 128);
    int* sDst  = sSrc + 128;

    int tid = threadIdx.x;
    int e0b = blockIdx.x * 128;

    load_w_padded(sW1, Wf1, 1600, tid, 512);
    load_w_padded(sW2, Wf2, 4096, tid, 512);
    for (int idx = tid; idx < 128 * NG; idx += 512) {
        int e = idx / NG, k = idx - e * NG;
        sEA[e * EA_S + k] = g_ea[(size_t)e0b * NG + idx];
    }
    if (tid < 128) {
        sC[tid]  = g_C[e0b + tid];
        sB1[tid] = bf1[tid];
        sB2[tid] = bf2[tid];
        sSrc[tid] = ei[e0b + tid];
        sDst[tid] = ei[N_EDGES + e0b + tid];
    }
    __syncthreads();

    int cg = tid & 7, eg = tid >> 3;   // 8 col-groups x 64 edge-groups
    int c0 = cg * 16, e0 = eg * 2;
    int wg = cg * 20;

    unsigned long long acc[2][8];
#pragma unroll
    for (int e = 0; e < 2; e++)
#pragma unroll
        for (int j = 0; j < 8; j++) acc[e][j] = 0ull;

    // ---- phase 1: T = ssp(EA @ W1 + b1) ----
#pragma unroll 5
    for (int k = 0; k < NG; k++) {
        unsigned long long a2[2];
#pragma unroll
        for (int e = 0; e < 2; e++) {
            float a = sEA[(e0 + e) * EA_S + k];
            a2[e] = pack2(a, a);
        }
        const ulonglong2* wp = (const ulonglong2*)(sW1 + k * W_S + wg);
        ulonglong2 w01 = wp[0], w23 = wp[1], w45 = wp[2], w67 = wp[3];
#pragma unroll
        for (int e = 0; e < 2; e++) {
            fma2(acc[e][0], a2[e], w01.x); fma2(acc[e][1], a2[e], w01.y);
            fma2(acc[e][2], a2[e], w23.x); fma2(acc[e][3], a2[e], w23.y);
            fma2(acc[e][4], a2[e], w45.x); fma2(acc[e][5], a2[e], w45.y);
            fma2(acc[e][6], a2[e], w67.x); fma2(acc[e][7], a2[e], w67.y);
        }
    }
#pragma unroll
    for (int e = 0; e < 2; e++) {
        float* trow = sT + (e0 + e) * T_S + c0;
#pragma unroll
        for (int q = 0; q < 4; q++) {
            float2 p0 = unpack2(acc[e][2 * q]);
            float2 p1 = unpack2(acc[e][2 * q + 1]);
            trow[4 * q + 0] = sspf(p0.x + sB1[c0 + 4 * q + 0]);
            trow[4 * q + 1] = sspf(p0.y + sB1[c0 + 4 * q + 1]);
            trow[4 * q + 2] = sspf(p1.x + sB1[c0 + 4 * q + 2]);
            trow[4 * q + 3] = sspf(p1.y + sB1[c0 + 4 * q + 3]);
        }
    }
    __syncthreads();

    // ---- phase 2: Wf = (T @ W2 + b2)*C; msg = x[src]*Wf; atomicAdd into agg[dst] ----
#pragma unroll
    for (int e = 0; e < 2; e++)
#pragma unroll
        for (int j = 0; j < 8; j++) acc[e][j] = 0ull;

#pragma unroll 4
    for (int k = 0; k < HID; k++) {
        unsigned long long a2[2];
#pragma unroll
        for (int e = 0; e < 2; e++) {
            float a = sT[(e0 + e) * T_S + k];
            a2[e] = pack2(a, a);
        }
        const ulonglong2* wp = (const ulonglong2*)(sW2 + k * W_S + wg);
        ulonglong2 w01 = wp[0], w23 = wp[1], w45 = wp[2], w67 = wp[3];
#pragma unroll
        for (int e = 0; e < 2; e++) {
            fma2(acc[e][0], a2[e], w01.x); fma2(acc[e][1], a2[e], w01.y);
            fma2(acc[e][2], a2[e], w23.x); fma2(acc[e][3], a2[e], w23.y);
            fma2(acc[e][4], a2[e], w45.x); fma2(acc[e][5], a2[e], w45.y);
            fma2(acc[e][6], a2[e], w67.x); fma2(acc[e][7], a2[e], w67.y);
        }
    }
#pragma unroll
    for (int e = 0; e < 2; e++) {
        int le = e0 + e;
        float Cv = sC[le];
        int s = sSrc[le];
        int d = sDst[le];
        const float4* xp = (const float4*)(g_x + (size_t)s * HID + c0);
        float* ap = g_agg + (size_t)d * HID + c0;
#pragma unroll
        for (int q = 0; q < 4; q++) {
            float2 p0 = unpack2(acc[e][2 * q]);
            float2 p1 = unpack2(acc[e][2 * q + 1]);
            float4 xv = xp[q];
            atomicAdd(ap + 4 * q + 0, (p0.x + sB2[c0 + 4 * q + 0]) * Cv * xv.x);
            atomicAdd(ap + 4 * q + 1, (p0.y + sB2[c0 + 4 * q + 1]) * Cv * xv.y);
            atomicAdd(ap + 4 * q + 2, (p1.x + sB2[c0 + 4 * q + 2]) * Cv * xv.z);
            atomicAdd(ap + 4 * q + 3, (p1.y + sB2[c0 + 4 * q + 3]) * Cv * xv.w);
        }
    }
}

// ---------------- K3: h = h + ssp(agg @ Wl2 + bl2) @ Wl + bl ----------------
// sA and sM overlay one buffer (regs hold GEMM1 result across a barrier).
#define SMEM_NODE ((2 * 128 * W_S + 64 * H_S + 256) * 4)
__global__ __launch_bounds__(256) void node_kernel(const float* __restrict__ Wl2,
                                                   const float* __restrict__ bl2,
                                                   const float* __restrict__ Wl,
                                                   const float* __restrict__ bl) {
    extern __shared__ float sm[];
    float* sWa = sm;                      // Wl2, 128 x W_S
    float* sWb = sWa + 128 * W_S;         // Wl,  128 x W_S
    float* sAM = sWb + 128 * W_S;         // 64 x H_S (agg, then ssp result)
    float* sB2 = sAM + 64 * H_S;
    float* sB  = sB2 + 128;

    int tid = threadIdx.x;
    int r0b = blockIdx.x * 64;

    load_w_padded(sWa, Wl2, 4096, tid, 256);
    load_w_padded(sWb, Wl, 4096, tid, 256);
    {
        const float4* asrc = (const float4*)(g_agg + (size_t)r0b * HID);
        for (int idx = tid; idx < 2048; idx += 256) {
            int r = idx >> 5, q = idx & 31;
            ((float4*)(sAM + r * H_S))[q] = asrc[idx];
        }
    }
    if (tid < 128) { sB2[tid] = bl2[tid]; sB[tid] = bl[tid]; }
    __syncthreads();

    int cg = tid & 7, rg = tid >> 3;
    int c0 = cg * 16, r0 = rg * 2;
    int wg = cg * 20;

    unsigned long long acc[2][8];
#pragma unroll
    for (int r = 0; r < 2; r++)
#pragma unroll
        for (int j = 0; j < 8; j++) acc[r][j] = 0ull;

#pragma unroll 4
    for (int k = 0; k < HID; k++) {
        unsigned long long a2[2];
#pragma unroll
        for (int r = 0; r < 2; r++) {
            float a = sAM[(r0 + r) * H_S + k];
            a2[r] = pack2(a, a);
        }
        const ulonglong2* wp = (const ulonglong2*)(sWa + k * W_S + wg);
        ulonglong2 w01 = wp[0], w23 = wp[1], w45 = wp[2], w67 = wp[3];
#pragma unroll
        for (int r = 0; r < 2; r++) {
            fma2(acc[r][0], a2[r], w01.x); fma2(acc[r][1], a2[r], w01.y);
            fma2(acc[r][2], a2[r], w23.x); fma2(acc[r][3], a2[r], w23.y);
            fma2(acc[r][4], a2[r], w45.x); fma2(acc[r][5], a2[r], w45.y);
            fma2(acc[r][6], a2[r], w67.x); fma2(acc[r][7], a2[r], w67.y);
        }
    }
    __syncthreads();   // everyone done READING sAM before it is overwritten
#pragma unroll
    for (int r = 0; r < 2; r++) {
        float* mrow = sAM + (r0 + r) * H_S + c0;
#pragma unroll
        for (int q = 0; q < 4; q++) {
            float2 p0 = unpack2(acc[r][2 * q]);
            float2 p1 = unpack2(acc[r][2 * q + 1]);
            float4 v;
            v.x = sspf(p0.x + sB2[c0 + 4 * q + 0]);
            v.y = sspf(p0.y + sB2[c0 + 4 * q + 1]);
            v.z = sspf(p1.x + sB2[c0 + 4 * q + 2]);
            v.w = sspf(p1.y + sB2[c0 + 4 * q + 3]);
            ((float4*)mrow)[q] = v;
        }
    }
    __syncthreads();

#pragma unroll
    for (int r = 0; r < 2; r++)
#pragma unroll
        for (int j = 0; j < 8; j++) acc[r][j] = 0ull;

#pragma unroll 4
    for (int k = 0; k < HID; k++) {
        unsigned long long a2[2];
#pragma unroll
        for (int r = 0; r < 2; r++) {
            float a = sAM[(r0 + r) * H_S + k];
            a2[r] = pack2(a, a);
        }
        const ulonglong2* wp = (const ulonglong2*)(sWb + k * W_S + wg);
        ulonglong2 w01 = wp[0], w23 = wp[1], w45 = wp[2], w67 = wp[3];
#pragma unroll
        for (int r = 0; r < 2; r++) {
            fma2(acc[r][0], a2[r], w01.x); fma2(acc[r][1], a2[r], w01.y);
            fma2(acc[r][2], a2[r], w23.x); fma2(acc[r][3], a2[r], w23.y);
            fma2(acc[r][4], a2[r], w45.x); fma2(acc[r][5], a2[r], w45.y);
            fma2(acc[r][6], a2[r], w67.x); fma2(acc[r][7], a2[r], w67.y);
        }
    }
#pragma unroll
    for (int r = 0; r < 2; r++) {
        float4* hp = (float4*)(g_h + (size_t)(r0b + r0 + r) * HID + c0);
#pragma unroll
        for (int q = 0; q < 4; q++) {
            float2 p0 = unpack2(acc[r][2 * q]);
            float2 p1 = unpack2(acc[r][2 * q + 1]);
            float4 h = hp[q];
            h.x += p0.x + sB[c0 + 4 * q + 0];
            h.y += p0.y + sB[c0 + 4 * q + 1];
            h.z += p1.x + sB[c0 + 4 * q + 2];
            h.w += p1.y + sB[c0 + 4 * q + 3];
            hp[q] = h;
        }
    }
}

// ---------------- K4: per-atom readout, per-block partial sums ----------------
__global__ __launch_bounds__(128) void readout_kernel(const float* __restrict__ Wo1,
                                                      const float* __restrict__ bo1,
                                                      const float* __restrict__ Wo2) {
    __shared__ float sW[128 * 64];
    __shared__ float sw2[64];
    __shared__ float sb1[64];
    __shared__ float wsum[4];
    int tid = threadIdx.x;
    for (int idx = tid; idx < 2048; idx += 128)
        ((float4*)sW)[idx] = ((const float4*)Wo1)[idx];
    if (tid < 64) { sw2[tid] = Wo2[tid]; sb1[tid] = bo1[tid]; }
    __syncthreads();

    int atom = blockIdx.x * 128 + tid;
    float acc[64];
#pragma unroll
    for (int j = 0; j < 64; j++) acc[j] = 0.0f;
    const float4* hp = (const float4*)(g_h + (size_t)atom * HID);
#pragma unroll 2
    for (int k4 = 0; k4 < 32; k4++) {
        float4 hv = hp[k4];
        const float* w0 = sW + (k4 * 4) * 64;
#pragma unroll
        for (int j = 0; j < 64; j++)
            acc[j] += hv.x * w0[j] + hv.y * w0[64 + j] + hv.z * w0[128 + j] + hv.w * w0[192 + j];
    }
    float s = 0.0f;
#pragma unroll
    for (int j = 0; j < 64; j++) s += sspf(acc[j] + sb1[j]) * sw2[j];

    for (int o = 16; o > 0; o >>= 1) s += __shfl_down_sync(0xffffffffu, s, o);
    if ((tid & 31) == 0) wsum[tid >> 5] = s;
    __syncthreads();
    if (tid == 0) g_bsum[blockIdx.x] = wsum[0] + wsum[1] + wsum[2] + wsum[3];
}

__global__ void finalize_kernel(const float* __restrict__ bo2, float* __restrict__ out) {
    __shared__ float ws[4];
    int tid = threadIdx.x;  // 128
    float v = g_bsum[tid];
    for (int o = 16; o > 0; o >>= 1) v += __shfl_down_sync(0xffffffffu, v, o);
    if ((tid & 31) == 0) ws[tid >> 5] = v;
    __syncthreads();
    if (tid == 0) {
        float t = ws[0] + ws[1] + ws[2] + ws[3] + (float)N_ATOMS * bo2[0];
        out[0] = fmaxf(t, 0.0f);
    }
}

// ---------------- launch ----------------
extern "C" void kernel_launch(void* const* d_in, const int* in_sizes, int n_in,
                              void* d_out, int out_size) {
    const int*   z    = (const int*)d_in[0];
    const float* pos  = (const float*)d_in[1];
    const int*   ei   = (const int*)d_in[2];
    const float* emb  = (const float*)d_in[3];
    const float* Wf1  = (const float*)d_in[4];
    const float* bf1  = (const float*)d_in[5];
    const float* Wf2  = (const float*)d_in[6];
    const float* bf2  = (const float*)d_in[7];
    const float* Wl1  = (const float*)d_in[8];
    const float* Wl2  = (const float*)d_in[9];
    const float* bl2  = (const float*)d_in[10];
    const float* Wl   = (const float*)d_in[11];
    const float* bl   = (const float*)d_in[12];
    const float* Wo1  = (const float*)d_in[13];
    const float* bo1  = (const float*)d_in[14];
    const float* Wo2  = (const float*)d_in[15];
    const float* bo2  = (const float*)d_in[16];
    float* out = (float*)d_out;

    cudaFuncSetAttribute(lin1_kernel, cudaFuncAttributeMaxDynamicSharedMemorySize, SMEM_LIN1);
    cudaFuncSetAttribute(edge_kernel, cudaFuncAttributeMaxDynamicSharedMemorySize, SMEM_EDGE);
    cudaFuncSetAttribute(node_kernel, cudaFuncAttributeMaxDynamicSharedMemorySize, SMEM_NODE);

    geom_kernel<<<(N_EDGES * NG) / 256, 256>>>(ei, pos);
    init_h_kernel<<<(N_ATOMS * HID) / 256, 256>>>(z, emb);

    for (int i = 0; i < NINTER; i++) {
        lin1_kernel<<<N_ATOMS / 64, 256, SMEM_LIN1>>>(Wl1 + i * 16384);
        edge_kernel<<<N_EDGES / 128, 512, SMEM_EDGE>>>(Wf1 + i * 6400, bf1 + i * 128,
                                                       Wf2 + i * 16384, bf2 + i * 128, ei);
        node_kernel<<<N_ATOMS / 64, 256, SMEM_NODE>>>(Wl2 + i * 16384, bl2 + i * 128,
                                                      Wl + i * 16384, bl + i * 128);
    }
    readout_kernel<<<N_ATOMS / 128, 128>>>(Wo1, bo1, Wo2);
    finalize_kernel<<<1, 128>>>(bo2, out);
}